// round 6
// baseline (speedup 1.0000x reference)
#include <cuda_runtime.h>
#include <cuda_fp16.h>
#include <cstdint>

// Problem constants
#define NE       1024   // experts
#define NB       1024   // batch
#define NH       64     // hidden width
#define WARPS    8
#define THREADS  256
#define RPW      128    // rows per warp  (NB / WARPS)
#define CHUNKS   8      // m16 chunks per warp (RPW / 16)
#define LDA      72     // padded halves per SMEM row (144 B -> conflict-free ldmatrix)

struct Smem {
    __half Wt[NH][LDA];             // Wt[o][j] = W2[j][o]  (B, col-major view)
    __half A[WARPS][2][16][LDA];    // per-warp DOUBLE-BUFFERED fp16 h tile
    float  b2s[NH];
    float  W3s[NH];
};

static __device__ __forceinline__ uint32_t smem_u32(const void* p) {
    uint32_t a;
    asm("{ .reg .u64 t; cvta.to.shared.u64 t, %1; cvt.u32.u64 %0, t; }"
        : "=r"(a) : "l"(p));
    return a;
}

// h = sigmoid(4u-2) = 0.5 + 0.5*tanh(2u-1): one MUFU.TANH per 2 elements (f16x2)
static __device__ __forceinline__ uint32_t sig2_h(float a, float b) {
    __half2 t = __floats2half2_rn(2.0f * a - 1.0f, 2.0f * b - 1.0f);
    uint32_t ti = *(uint32_t*)&t, to;
    asm("tanh.approx.f16x2 %0, %1;" : "=r"(to) : "r"(ti));
    __half2 th = *(__half2*)&to;
    __half2 hv = __hfma2(th, __half2half2(__float2half(0.5f)),
                             __half2half2(__float2half(0.5f)));
    return *(uint32_t*)&hv;
}

// fp32 tanh.approx (1 MUFU) for the epilogue sigmoid
static __device__ __forceinline__ float tanhf_approx(float x) {
    float y;
    asm("tanh.approx.f32 %0, %1;" : "=f"(y) : "f"(x));
    return y;
}

static __device__ __forceinline__ void ldsm_x4(uint32_t* r, uint32_t addr) {
    asm volatile("ldmatrix.sync.aligned.m8n8.x4.shared.b16 {%0,%1,%2,%3}, [%4];"
                 : "=r"(r[0]), "=r"(r[1]), "=r"(r[2]), "=r"(r[3]) : "r"(addr));
}
static __device__ __forceinline__ void ldsm_x2(uint32_t& b0, uint32_t& b1,
                                               uint32_t addr) {
    asm volatile("ldmatrix.sync.aligned.m8n8.x2.shared.b16 {%0,%1}, [%2];"
                 : "=r"(b0), "=r"(b1) : "r"(addr));
}
static __device__ __forceinline__ void mma16816(float& c0, float& c1, float& c2,
                                                float& c3, const uint32_t* a,
                                                uint32_t b0, uint32_t b1) {
    asm volatile(
        "mma.sync.aligned.m16n8k16.row.col.f32.f16.f16.f32 "
        "{%0,%1,%2,%3}, {%4,%5,%6,%7}, {%8,%9}, {%0,%1,%2,%3};"
        : "+f"(c0), "+f"(c1), "+f"(c2), "+f"(c3)
        : "r"(a[0]), "r"(a[1]), "r"(a[2]), "r"(a[3]), "r"(b0), "r"(b1));
}

// ---------------------------------------------------------------------------
// One block = one expert; warp w owns rows [w*128, w*128+128), 8 m16 chunks.
// B fragments in registers (once per expert). Main loop is software-pipelined:
// ldsm A(ch) first, then convert(ch+1) [issues next LDGs early -> DRAM latency
// hidden behind MMA+epilogue of ch], then MMA + tanh-epilogue + strided write.
// ---------------------------------------------------------------------------
__global__ __launch_bounds__(THREADS, 2)
void golem_hmma_kernel(const float* __restrict__ noise,   // [E, B, H]
                       const float* __restrict__ W2,      // [E, H, H]
                       const float* __restrict__ b2,      // [E, H]
                       const float* __restrict__ W3,      // [E, H]
                       const float* __restrict__ b3,      // [E]
                       const float* __restrict__ T,       // [B]
                       const float* __restrict__ alpha,
                       const float* __restrict__ beta,
                       const float* __restrict__ bias,
                       float* __restrict__ out)           // [B,E] + [B]
{
    __shared__ Smem s;
    const int e   = blockIdx.x;
    const int tid = threadIdx.x;
    const int w   = tid >> 5;
    const int l   = tid & 31;

    // T_embed piggybacks on block 0
    if (e == 0) {
        float inva = __fdividef(1.0f, alpha[0]);
        float be = beta[0], bi = bias[0];
        for (int i = tid; i < NB; i += THREADS)
            out[(size_t)NB * NE + i] = inva * cosf(be * T[i] + bi);
    }

    // Stage W2[e] transposed -> Wt[o][j] fp16
    const float* W2e = W2 + (size_t)e * NH * NH;
    for (int i = tid; i < NH * NH; i += THREADS) {
        int j = i >> 6, o = i & 63;
        s.Wt[o][j] = __float2half_rn(W2e[i]);
    }
    if (tid < NH) {
        s.b2s[tid] = b2[(size_t)e * NH + tid];
        s.W3s[tid] = W3[(size_t)e * NH + tid];
    }
    __syncthreads();

    // Epilogue constants for cols o = n*8 + 2*(l&3) + {0,1}:
    //   sigmoid(x) = 0.5 + 0.5*tanh(x/2)
    //   acc = sum_o W3[o]*sigmoid(c_o) = sum_o (W3[o]/2)*tanh(c_o/2) + sum_o W3[o]/2
    float   pw3h[16];        // W3/2
    float   w3base = 0.0f;   // sum over my 16 cols of W3/2
    __half2 pb2h[8];
    #pragma unroll
    for (int n = 0; n < 8; n++) {
        int o = n * 8 + 2 * (l & 3);
        pw3h[2 * n]     = 0.5f * s.W3s[o];
        pw3h[2 * n + 1] = 0.5f * s.W3s[o + 1];
        w3base += pw3h[2 * n] + pw3h[2 * n + 1];
        pb2h[n] = __floats2half2_rn(s.b2s[o], s.b2s[o + 1]);
    }
    const float b3e = b3[e];

    const uint32_t aB0    = smem_u32(&s.A[w][0][0][0]);
    const uint32_t aB1    = smem_u32(&s.A[w][1][0][0]);
    const uint32_t wtBase = smem_u32(&s.Wt[0][0]);
    // A ldmatrix (m16k16 row-major): lane -> row (l&15), 16B chunk (l>>4)
    const uint32_t aLdOff  = (uint32_t)(l & 15) * (LDA * 2) + (uint32_t)(l >> 4) * 16;
    // B ldmatrix (n8k16 from Wt rows = o): lanes 0..15 -> row (l&7), k-half ((l>>3)&1)
    const uint32_t bLd = wtBase + (uint32_t)(l & 7) * (LDA * 2) + (uint32_t)((l >> 3) & 1) * 16;
    // convert: lane l -> row l/2, halves (l&1)*32..+31
    const uint32_t cvtOff = (uint32_t)(l >> 1) * (LDA * 2) + (uint32_t)(l & 1) * 64;

    // ---- hoist B fragments: constant per expert, loaded once ----
    uint32_t bf[8][4][2];
    #pragma unroll
    for (int n = 0; n < 8; n++)
        #pragma unroll
        for (int ks = 0; ks < 4; ks++)
            ldsm_x2(bf[n][ks][0], bf[n][ks][1],
                    bLd + (uint32_t)n * 8 * (LDA * 2) + (uint32_t)ks * 32);

    const float* nbase = noise + ((size_t)e * NB + (size_t)w * RPW) * NH;

    // ---- converter for one 16-row chunk into buffer buf ----
    auto convert_tile = [&](int ch, int buf) {
        const float4* src = (const float4*)(nbase + ((size_t)ch * 16 + (l >> 1)) * NH
                                            + (l & 1) * 32);
        uint32_t dst = (buf ? aB1 : aB0) + cvtOff;
        #pragma unroll
        for (int i = 0; i < 4; i++) {
            float4 v0 = src[2 * i];
            float4 v1 = src[2 * i + 1];
            uint32_t p0 = sig2_h(v0.x, v0.y);
            uint32_t p1 = sig2_h(v0.z, v0.w);
            uint32_t p2 = sig2_h(v1.x, v1.y);
            uint32_t p3 = sig2_h(v1.z, v1.w);
            asm volatile("st.shared.v4.b32 [%0], {%1,%2,%3,%4};"
                         :: "r"(dst + (uint32_t)i * 16),
                            "r"(p0), "r"(p1), "r"(p2), "r"(p3) : "memory");
        }
    };

    // ---- pipelined main loop ----
    convert_tile(0, 0);

    #pragma unroll 1
    for (int ch = 0; ch < CHUNKS; ch++) {
        __syncwarp();   // A[buf] stores (from convert) visible to ldmatrix

        // A fragments for this chunk
        uint32_t a[4][4];
        const uint32_t aLd = ((ch & 1) ? aB1 : aB0) + aLdOff;
        #pragma unroll
        for (int ks = 0; ks < 4; ks++)
            ldsm_x4(a[ks], aLd + (uint32_t)ks * 32);

        // issue next chunk's LDGs NOW — latency hides behind MMA+epilogue
        if (ch + 1 < CHUNKS)
            convert_tile(ch + 1, (ch + 1) & 1);

        // GEMM + fused tanh epilogue per n-tile (B from registers)
        float acc0 = w3base, acc1 = w3base;   // rows l/4 and l/4+8
        #pragma unroll
        for (int n = 0; n < 8; n++) {
            float2 b2p = __half22float2(pb2h[n]);
            float c0 = b2p.x, c1 = b2p.y, c2 = b2p.x, c3 = b2p.y;
            #pragma unroll
            for (int ks = 0; ks < 4; ks++)
                mma16816(c0, c1, c2, c3, a[ks], bf[n][ks][0], bf[n][ks][1]);
            acc0 += tanhf_approx(0.5f * c0) * pw3h[2 * n];
            acc0 += tanhf_approx(0.5f * c1) * pw3h[2 * n + 1];
            acc1 += tanhf_approx(0.5f * c2) * pw3h[2 * n];
            acc1 += tanhf_approx(0.5f * c3) * pw3h[2 * n + 1];
        }

        // quad reduce over (l&3): columns are split across the 4 quad lanes
        acc0 += __shfl_xor_sync(0xffffffffu, acc0, 1);
        acc0 += __shfl_xor_sync(0xffffffffu, acc0, 2);
        acc1 += __shfl_xor_sync(0xffffffffu, acc1, 1);
        acc1 += __shfl_xor_sync(0xffffffffu, acc1, 2);

        if ((l & 3) == 0) {
            int r = w * RPW + ch * 16 + (l >> 2);
            __stcs(&out[(size_t)r * NE + e],       acc0 + b3e);
            __stcs(&out[(size_t)(r + 8) * NE + e], acc1 + b3e);
        }
    }
}

// ---------------------------------------------------------------------------
// kernel_launch — inputs: 0:T 1:noise 2:W1(dead) 3:W2 4:b2 5:W3 6:b3
//                          7:alpha 8:beta 9:bias.  Output fp32: B_mat[B,E] + T_embed[B]
// ---------------------------------------------------------------------------
extern "C" void kernel_launch(void* const* d_in, const int* in_sizes, int n_in,
                              void* d_out, int out_size)
{
    const float* T     = (const float*)d_in[0];
    const float* noise = (const float*)d_in[1];
    const float* W2    = (const float*)d_in[3];
    const float* b2    = (const float*)d_in[4];
    const float* W3    = (const float*)d_in[5];
    const float* b3    = (const float*)d_in[6];
    const float* alpha = (const float*)d_in[7];
    const float* beta  = (const float*)d_in[8];
    const float* bias  = (const float*)d_in[9];

    golem_hmma_kernel<<<NE, THREADS>>>(noise, W2, b2, W3, b3,
                                       T, alpha, beta, bias, (float*)d_out);
}

// round 7
// speedup vs baseline: 1.1792x; 1.1792x over previous
#include <cuda_runtime.h>
#include <cuda_fp16.h>
#include <cstdint>

// Problem constants
#define NE       1024   // experts
#define NB       1024   // batch
#define NH       64     // hidden width
#define WARPS    8
#define THREADS  256
#define RPW      128    // rows per warp  (NB / WARPS)
#define CHUNKS   8      // m16 chunks per warp (RPW / 16)
#define LDA      72     // padded halves per SMEM row (144 B -> conflict-free ldmatrix)

struct Smem {
    __half Wt[NH][LDA];          // Wt[o][j] = W2[j][o]  (B, col-major view)
    __half A[WARPS][16][LDA];    // per-warp fp16 h tile (single buffer)
    float  b2s[NH];
    float  W3s[NH];
};

static __device__ __forceinline__ uint32_t smem_u32(const void* p) {
    uint32_t a;
    asm("{ .reg .u64 t; cvta.to.shared.u64 t, %1; cvt.u32.u64 %0, t; }"
        : "=r"(a) : "l"(p));
    return a;
}

// h = sigmoid(4u-2) = 0.5 + 0.5*tanh(2u-1): one MUFU.TANH per 2 elements.
// PURE asm (no memory clobber) so it never blocks LDG hoisting.
static __device__ __forceinline__ uint32_t sig2_h(float a, float b) {
    __half2 t = __floats2half2_rn(2.0f * a - 1.0f, 2.0f * b - 1.0f);
    uint32_t ti = *(uint32_t*)&t, to;
    asm("tanh.approx.f16x2 %0, %1;" : "=r"(to) : "r"(ti));
    __half2 th = *(__half2*)&to;
    __half2 hv = __hfma2(th, __half2half2(__float2half(0.5f)),
                             __half2half2(__float2half(0.5f)));
    return *(uint32_t*)&hv;
}

// fp32 tanh.approx (1 MUFU) for the epilogue sigmoid
static __device__ __forceinline__ float tanhf_approx(float x) {
    float y;
    asm("tanh.approx.f32 %0, %1;" : "=f"(y) : "f"(x));
    return y;
}

static __device__ __forceinline__ void ldsm_x4(uint32_t* r, uint32_t addr) {
    asm volatile("ldmatrix.sync.aligned.m8n8.x4.shared.b16 {%0,%1,%2,%3}, [%4];"
                 : "=r"(r[0]), "=r"(r[1]), "=r"(r[2]), "=r"(r[3]) : "r"(addr) : "memory");
}
static __device__ __forceinline__ void ldsm_x2(uint32_t& b0, uint32_t& b1,
                                               uint32_t addr) {
    asm volatile("ldmatrix.sync.aligned.m8n8.x2.shared.b16 {%0,%1}, [%2];"
                 : "=r"(b0), "=r"(b1) : "r"(addr) : "memory");
}
static __device__ __forceinline__ void mma16816(float& c0, float& c1, float& c2,
                                                float& c3, const uint32_t* a,
                                                uint32_t b0, uint32_t b1) {
    asm volatile(
        "mma.sync.aligned.m16n8k16.row.col.f32.f16.f16.f32 "
        "{%0,%1,%2,%3}, {%4,%5,%6,%7}, {%8,%9}, {%0,%1,%2,%3};"
        : "+f"(c0), "+f"(c1), "+f"(c2), "+f"(c3)
        : "r"(a[0]), "r"(a[1]), "r"(a[2]), "r"(a[3]), "r"(b0), "r"(b1));
}

// ---------------------------------------------------------------------------
// One block = one expert; warp w owns rows [w*128, w*128+128), 8 m16 chunks.
// B fragments (W2^T) in registers once per expert. Convert path uses PLAIN
// loads/stores so ptxas front-batches the 8 LDG.128s (MLP=8, latency /4).
// ---------------------------------------------------------------------------
__global__ __launch_bounds__(THREADS, 2)
void golem_hmma_kernel(const float* __restrict__ noise,   // [E, B, H]
                       const float* __restrict__ W2,      // [E, H, H]
                       const float* __restrict__ b2,      // [E, H]
                       const float* __restrict__ W3,      // [E, H]
                       const float* __restrict__ b3,      // [E]
                       const float* __restrict__ T,       // [B]
                       const float* __restrict__ alpha,
                       const float* __restrict__ beta,
                       const float* __restrict__ bias,
                       float* __restrict__ out)           // [B,E] + [B]
{
    __shared__ Smem s;
    const int e   = blockIdx.x;
    const int tid = threadIdx.x;
    const int w   = tid >> 5;
    const int l   = tid & 31;

    // T_embed piggybacks on block 0
    if (e == 0) {
        float inva = __fdividef(1.0f, alpha[0]);
        float be = beta[0], bi = bias[0];
        for (int i = tid; i < NB; i += THREADS)
            out[(size_t)NB * NE + i] = inva * cosf(be * T[i] + bi);
    }

    // Stage W2[e] transposed -> Wt[o][j] fp16
    const float* W2e = W2 + (size_t)e * NH * NH;
    for (int i = tid; i < NH * NH; i += THREADS) {
        int j = i >> 6, o = i & 63;
        s.Wt[o][j] = __float2half_rn(W2e[i]);
    }
    if (tid < NH) {
        s.b2s[tid] = b2[(size_t)e * NH + tid];
        s.W3s[tid] = W3[(size_t)e * NH + tid];
    }
    __syncthreads();

    // Epilogue constants for cols o = n*8 + 2*(l&3) + {0,1}:
    //   sigmoid(x) = 0.5 + 0.5*tanh(x/2)
    //   acc = sum_o (W3[o]/2)*tanh(c_o/2) + sum_o W3[o]/2
    float   pw3h[16];        // W3/2
    float   w3base = 0.0f;   // sum over my 16 cols of W3/2
    __half2 pb2h[8];
    #pragma unroll
    for (int n = 0; n < 8; n++) {
        int o = n * 8 + 2 * (l & 3);
        pw3h[2 * n]     = 0.5f * s.W3s[o];
        pw3h[2 * n + 1] = 0.5f * s.W3s[o + 1];
        w3base += pw3h[2 * n] + pw3h[2 * n + 1];
        pb2h[n] = __floats2half2_rn(s.b2s[o], s.b2s[o + 1]);
    }
    const float b3e = b3[e];

    const uint32_t aBase  = smem_u32(&s.A[w][0][0]);
    const uint32_t wtBase = smem_u32(&s.Wt[0][0]);
    // A ldmatrix (m16k16 row-major): lane -> row (l&15), 16B chunk (l>>4)
    const uint32_t aLd = aBase + (uint32_t)(l & 15) * (LDA * 2) + (uint32_t)(l >> 4) * 16;
    // B ldmatrix (n8k16 from Wt rows = o): lanes 0..15 -> row (l&7), k-half ((l>>3)&1)
    const uint32_t bLd = wtBase + (uint32_t)(l & 7) * (LDA * 2) + (uint32_t)((l >> 3) & 1) * 16;
    // convert dst: lane l -> row l/2, halves (l&1)*32..+31  (16B aligned: 144B rows)
    uint4* const cvtDst = (uint4*)((__half*)&s.A[w][0][0] + (l >> 1) * LDA + (l & 1) * 32);

    // ---- hoist B fragments: constant per expert, loaded once ----
    uint32_t bf[8][4][2];
    #pragma unroll
    for (int n = 0; n < 8; n++)
        #pragma unroll
        for (int ks = 0; ks < 4; ks++)
            ldsm_x2(bf[n][ks][0], bf[n][ks][1],
                    bLd + (uint32_t)n * 8 * (LDA * 2) + (uint32_t)ks * 32);

    const float* nbase = noise + ((size_t)e * NB + (size_t)w * RPW) * NH;

    #pragma unroll 1
    for (int ch = 0; ch < CHUNKS; ch++) {
        __syncwarp();   // protect A tile vs previous chunk's ldmatrix

        // ---- convert 16 rows: plain loads/stores, compiler-batched LDGs ----
        const float4* src = (const float4*)(nbase + ((size_t)ch * 16 + (l >> 1)) * NH
                                            + (l & 1) * 32);
        float4 v[8];
        #pragma unroll
        for (int i = 0; i < 8; i++) v[i] = src[i];
        #pragma unroll
        for (int i = 0; i < 4; i++) {
            uint4 pk;
            pk.x = sig2_h(v[2 * i].x,     v[2 * i].y);
            pk.y = sig2_h(v[2 * i].z,     v[2 * i].w);
            pk.z = sig2_h(v[2 * i + 1].x, v[2 * i + 1].y);
            pk.w = sig2_h(v[2 * i + 1].z, v[2 * i + 1].w);
            cvtDst[i] = pk;
        }
        __syncwarp();

        // ---- A fragments: 4 K-steps ----
        uint32_t a[4][4];
        #pragma unroll
        for (int ks = 0; ks < 4; ks++)
            ldsm_x4(a[ks], aLd + (uint32_t)ks * 32);

        // ---- GEMM + fused tanh epilogue per n-tile (B from registers) ----
        float acc0 = w3base, acc1 = w3base;   // rows l/4 and l/4+8
        #pragma unroll
        for (int n = 0; n < 8; n++) {
            float2 b2p = __half22float2(pb2h[n]);
            float c0 = b2p.x, c1 = b2p.y, c2 = b2p.x, c3 = b2p.y;
            #pragma unroll
            for (int ks = 0; ks < 4; ks++)
                mma16816(c0, c1, c2, c3, a[ks], bf[n][ks][0], bf[n][ks][1]);
            acc0 += tanhf_approx(0.5f * c0) * pw3h[2 * n];
            acc0 += tanhf_approx(0.5f * c1) * pw3h[2 * n + 1];
            acc1 += tanhf_approx(0.5f * c2) * pw3h[2 * n];
            acc1 += tanhf_approx(0.5f * c3) * pw3h[2 * n + 1];
        }

        // quad reduce over (l&3): columns split across the 4 quad lanes
        acc0 += __shfl_xor_sync(0xffffffffu, acc0, 1);
        acc0 += __shfl_xor_sync(0xffffffffu, acc0, 2);
        acc1 += __shfl_xor_sync(0xffffffffu, acc1, 1);
        acc1 += __shfl_xor_sync(0xffffffffu, acc1, 2);

        if ((l & 3) == 0) {
            int r = w * RPW + ch * 16 + (l >> 2);
            out[(size_t)r * NE + e]       = acc0 + b3e;
            out[(size_t)(r + 8) * NE + e] = acc1 + b3e;
        }
    }
}

// ---------------------------------------------------------------------------
// kernel_launch — inputs: 0:T 1:noise 2:W1(dead) 3:W2 4:b2 5:W3 6:b3
//                          7:alpha 8:beta 9:bias.  Output fp32: B_mat[B,E] + T_embed[B]
// ---------------------------------------------------------------------------
extern "C" void kernel_launch(void* const* d_in, const int* in_sizes, int n_in,
                              void* d_out, int out_size)
{
    const float* T     = (const float*)d_in[0];
    const float* noise = (const float*)d_in[1];
    const float* W2    = (const float*)d_in[3];
    const float* b2    = (const float*)d_in[4];
    const float* W3    = (const float*)d_in[5];
    const float* b3    = (const float*)d_in[6];
    const float* alpha = (const float*)d_in[7];
    const float* beta  = (const float*)d_in[8];
    const float* bias  = (const float*)d_in[9];

    golem_hmma_kernel<<<NE, THREADS>>>(noise, W2, b2, W3, b3,
                                       T, alpha, beta, bias, (float*)d_out);
}

// round 8
// speedup vs baseline: 1.3400x; 1.1364x over previous
#include <cuda_runtime.h>
#include <cuda_fp16.h>
#include <cstdint>

// Problem constants
#define NE       1024   // experts
#define NB       1024   // batch
#define NH       64     // hidden width
#define WARPS    8
#define THREADS  256
#define RPW      128    // rows per warp  (NB / WARPS)
#define CHUNKS   8      // m16 chunks per warp (RPW / 16)
#define LDA      72     // padded halves per SMEM row (144 B -> conflict-free ldmatrix)

struct Smem {
    __half Wt[NH][LDA];          // Wt[o][j] = W2[j][o]  (B, col-major view)
    __half A[WARPS][16][LDA];    // per-warp fp16 h tile (single buffer)
    float  b2s[NH];
    float  W3s[NH];
};

static __device__ __forceinline__ uint32_t smem_u32(const void* p) {
    uint32_t a;
    asm("{ .reg .u64 t; cvta.to.shared.u64 t, %1; cvt.u32.u64 %0, t; }"
        : "=r"(a) : "l"(p));
    return a;
}

// h = sigmoid(4u-2) = 0.5 + 0.5*tanh(2u-1): one MUFU.TANH per 2 elements.
// Pure asm (no memory clobber) so it never blocks LDG batching.
static __device__ __forceinline__ uint32_t sig2_h(float a, float b) {
    __half2 t = __floats2half2_rn(2.0f * a - 1.0f, 2.0f * b - 1.0f);
    uint32_t ti = *(uint32_t*)&t, to;
    asm("tanh.approx.f16x2 %0, %1;" : "=r"(to) : "r"(ti));
    __half2 th = *(__half2*)&to;
    __half2 hv = __hfma2(th, __half2half2(__float2half(0.5f)),
                             __half2half2(__float2half(0.5f)));
    return *(uint32_t*)&hv;
}

// fp32 tanh.approx (1 MUFU) for the epilogue sigmoid
static __device__ __forceinline__ float tanhf_approx(float x) {
    float y;
    asm("tanh.approx.f32 %0, %1;" : "=f"(y) : "f"(x));
    return y;
}

static __device__ __forceinline__ void ldsm_x4(uint32_t* r, uint32_t addr) {
    asm volatile("ldmatrix.sync.aligned.m8n8.x4.shared.b16 {%0,%1,%2,%3}, [%4];"
                 : "=r"(r[0]), "=r"(r[1]), "=r"(r[2]), "=r"(r[3]) : "r"(addr) : "memory");
}
static __device__ __forceinline__ void ldsm_x2(uint32_t& b0, uint32_t& b1,
                                               uint32_t addr) {
    asm volatile("ldmatrix.sync.aligned.m8n8.x2.shared.b16 {%0,%1}, [%2];"
                 : "=r"(b0), "=r"(b1) : "r"(addr) : "memory");
}
static __device__ __forceinline__ void mma16816(float& c0, float& c1, float& c2,
                                                float& c3, const uint32_t* a,
                                                uint32_t b0, uint32_t b1) {
    asm volatile(
        "mma.sync.aligned.m16n8k16.row.col.f32.f16.f16.f32 "
        "{%0,%1,%2,%3}, {%4,%5,%6,%7}, {%8,%9}, {%0,%1,%2,%3};"
        : "+f"(c0), "+f"(c1), "+f"(c2), "+f"(c3)
        : "r"(a[0]), "r"(a[1]), "r"(a[2]), "r"(a[3]), "r"(b0), "r"(b1));
}

// ---------------------------------------------------------------------------
// One block = one expert; warp w owns rows [w*128, w*128+128), 8 m16 chunks.
// B fragments (W2^T) in registers once per expert.
// Convert mapping is FULLY COALESCED: LDG i covers rows {2i, 2i+1} with
// lane -> (row 2i + l/16, cols (l%16)*4): 4 L1 wavefronts per LDG.128
// instead of 32 with the old row-per-lane-pair mapping.
// ---------------------------------------------------------------------------
__global__ __launch_bounds__(THREADS, 2)
void golem_hmma_kernel(const float* __restrict__ noise,   // [E, B, H]
                       const float* __restrict__ W2,      // [E, H, H]
                       const float* __restrict__ b2,      // [E, H]
                       const float* __restrict__ W3,      // [E, H]
                       const float* __restrict__ b3,      // [E]
                       const float* __restrict__ T,       // [B]
                       const float* __restrict__ alpha,
                       const float* __restrict__ beta,
                       const float* __restrict__ bias,
                       float* __restrict__ out)           // [B,E] + [B]
{
    __shared__ Smem s;
    const int e   = blockIdx.x;
    const int tid = threadIdx.x;
    const int w   = tid >> 5;
    const int l   = tid & 31;

    // T_embed piggybacks on block 0
    if (e == 0) {
        float inva = __fdividef(1.0f, alpha[0]);
        float be = beta[0], bi = bias[0];
        for (int i = tid; i < NB; i += THREADS)
            out[(size_t)NB * NE + i] = inva * cosf(be * T[i] + bi);
    }

    // Stage W2[e] transposed -> Wt[o][j] fp16
    const float* W2e = W2 + (size_t)e * NH * NH;
    for (int i = tid; i < NH * NH; i += THREADS) {
        int j = i >> 6, o = i & 63;
        s.Wt[o][j] = __float2half_rn(W2e[i]);
    }
    if (tid < NH) {
        s.b2s[tid] = b2[(size_t)e * NH + tid];
        s.W3s[tid] = W3[(size_t)e * NH + tid];
    }
    __syncthreads();

    // Epilogue constants for cols o = n*8 + 2*(l&3) + {0,1}:
    //   sigmoid(x) = 0.5 + 0.5*tanh(x/2)
    //   acc = sum_o (W3[o]/2)*tanh(c_o/2) + sum_o W3[o]/2
    float   pw3h[16];        // W3/2
    float   w3base = 0.0f;   // sum over my 16 cols of W3/2
    __half2 pb2h[8];
    #pragma unroll
    for (int n = 0; n < 8; n++) {
        int o = n * 8 + 2 * (l & 3);
        pw3h[2 * n]     = 0.5f * s.W3s[o];
        pw3h[2 * n + 1] = 0.5f * s.W3s[o + 1];
        w3base += pw3h[2 * n] + pw3h[2 * n + 1];
        pb2h[n] = __floats2half2_rn(s.b2s[o], s.b2s[o + 1]);
    }
    const float b3e = b3[e];

    const uint32_t aBase  = smem_u32(&s.A[w][0][0]);
    const uint32_t wtBase = smem_u32(&s.Wt[0][0]);
    // A ldmatrix (m16k16 row-major): lane -> row (l&15), 16B chunk (l>>4)
    const uint32_t aLd = aBase + (uint32_t)(l & 15) * (LDA * 2) + (uint32_t)(l >> 4) * 16;
    // B ldmatrix (n8k16 from Wt rows = o): lanes 0..15 -> row (l&7), k-half ((l>>3)&1)
    const uint32_t bLd = wtBase + (uint32_t)(l & 7) * (LDA * 2) + (uint32_t)((l >> 3) & 1) * 16;

    // ---- hoist B fragments: constant per expert, loaded once ----
    uint32_t bf[8][4][2];
    #pragma unroll
    for (int n = 0; n < 8; n++)
        #pragma unroll
        for (int ks = 0; ks < 4; ks++)
            ldsm_x2(bf[n][ks][0], bf[n][ks][1],
                    bLd + (uint32_t)n * 8 * (LDA * 2) + (uint32_t)ks * 32);

    // Coalesced convert mapping: lane l -> sub-row (l>>4), float col (l&15)*4
    const float* nbase = noise + ((size_t)e * NB + (size_t)w * RPW) * NH;
    const float4* csrc = (const float4*)(nbase + (size_t)(l >> 4) * NH) + (l & 15);
    uint2* const cdst = (uint2*)((__half*)&s.A[w][0][0] + (l >> 4) * LDA + (l & 15) * 4);

    #pragma unroll 1
    for (int ch = 0; ch < CHUNKS; ch++) {
        __syncwarp();   // protect A tile vs previous chunk's ldmatrix

        // ---- convert 16 rows, fully coalesced ----
        float4 v[8];
        #pragma unroll
        for (int i = 0; i < 8; i++)
            v[i] = csrc[(size_t)(ch * 16 + 2 * i) * (NH / 4)];
        #pragma unroll
        for (int i = 0; i < 8; i++) {
            uint2 pk;
            pk.x = sig2_h(v[i].x, v[i].y);
            pk.y = sig2_h(v[i].z, v[i].w);
            cdst[(size_t)(2 * i) * (LDA / 4)] = pk;
        }
        __syncwarp();

        // ---- A fragments: 4 K-steps ----
        uint32_t a[4][4];
        #pragma unroll
        for (int ks = 0; ks < 4; ks++)
            ldsm_x4(a[ks], aLd + (uint32_t)ks * 32);

        // ---- GEMM + fused tanh epilogue per n-tile (B from registers) ----
        float acc0 = w3base, acc1 = w3base;   // rows l/4 and l/4+8
        #pragma unroll
        for (int n = 0; n < 8; n++) {
            float2 b2p = __half22float2(pb2h[n]);
            float c0 = b2p.x, c1 = b2p.y, c2 = b2p.x, c3 = b2p.y;
            #pragma unroll
            for (int ks = 0; ks < 4; ks++)
                mma16816(c0, c1, c2, c3, a[ks], bf[n][ks][0], bf[n][ks][1]);
            acc0 += tanhf_approx(0.5f * c0) * pw3h[2 * n];
            acc0 += tanhf_approx(0.5f * c1) * pw3h[2 * n + 1];
            acc1 += tanhf_approx(0.5f * c2) * pw3h[2 * n];
            acc1 += tanhf_approx(0.5f * c3) * pw3h[2 * n + 1];
        }

        // quad reduce over (l&3): columns split across the 4 quad lanes
        acc0 += __shfl_xor_sync(0xffffffffu, acc0, 1);
        acc0 += __shfl_xor_sync(0xffffffffu, acc0, 2);
        acc1 += __shfl_xor_sync(0xffffffffu, acc1, 1);
        acc1 += __shfl_xor_sync(0xffffffffu, acc1, 2);

        if ((l & 3) == 0) {
            int r = w * RPW + ch * 16 + (l >> 2);
            out[(size_t)r * NE + e]       = acc0 + b3e;
            out[(size_t)(r + 8) * NE + e] = acc1 + b3e;
        }
    }
}

// ---------------------------------------------------------------------------
// kernel_launch — inputs: 0:T 1:noise 2:W1(dead) 3:W2 4:b2 5:W3 6:b3
//                          7:alpha 8:beta 9:bias.  Output fp32: B_mat[B,E] + T_embed[B]
// ---------------------------------------------------------------------------
extern "C" void kernel_launch(void* const* d_in, const int* in_sizes, int n_in,
                              void* d_out, int out_size)
{
    const float* T     = (const float*)d_in[0];
    const float* noise = (const float*)d_in[1];
    const float* W2    = (const float*)d_in[3];
    const float* b2    = (const float*)d_in[4];
    const float* W3    = (const float*)d_in[5];
    const float* b3    = (const float*)d_in[6];
    const float* alpha = (const float*)d_in[7];
    const float* beta  = (const float*)d_in[8];
    const float* bias  = (const float*)d_in[9];

    golem_hmma_kernel<<<NE, THREADS>>>(noise, W2, b2, W3, b3,
                                       T, alpha, beta, bias, (float*)d_out);
}

// round 9
// speedup vs baseline: 1.5851x; 1.1829x over previous
#include <cuda_runtime.h>
#include <cuda_fp16.h>
#include <cstdint>

// Problem constants
#define NE       1024   // experts
#define NB       1024   // batch
#define NH       64     // hidden width
#define WARPS    8
#define THREADS  256
#define RPW      128    // rows per warp  (NB / WARPS)
#define CHUNKS   8      // m16 chunks per warp (RPW / 16)
#define LDA      72     // padded halves per SMEM row (144 B -> conflict-free ldmatrix)

struct Smem {
    __half Wt[NH][LDA];             // 9216 B : Wt[o][j] = W2[j][o]
    __half A[WARPS][16][LDA];       // 18432 B: per-warp fp16 h tile
    float  raw[WARPS][2][16][NH];   // 65536 B: per-warp double-buffered raw noise
    float  b2s[NH];
    float  W3s[NH];
};

static __device__ __forceinline__ uint32_t smem_u32(const void* p) {
    uint32_t a;
    asm("{ .reg .u64 t; cvta.to.shared.u64 t, %1; cvt.u32.u64 %0, t; }"
        : "=r"(a) : "l"(p));
    return a;
}

// h = sigmoid(4u-2) = 0.5 + 0.5*tanh(2u-1): one MUFU.TANH per 2 elements.
static __device__ __forceinline__ uint32_t sig2_h(float a, float b) {
    __half2 t = __floats2half2_rn(2.0f * a - 1.0f, 2.0f * b - 1.0f);
    uint32_t ti = *(uint32_t*)&t, to;
    asm("tanh.approx.f16x2 %0, %1;" : "=r"(to) : "r"(ti));
    __half2 th = *(__half2*)&to;
    __half2 hv = __hfma2(th, __half2half2(__float2half(0.5f)),
                             __half2half2(__float2half(0.5f)));
    return *(uint32_t*)&hv;
}

// fp32 tanh.approx (1 MUFU) for the epilogue sigmoid
static __device__ __forceinline__ float tanhf_approx(float x) {
    float y;
    asm("tanh.approx.f32 %0, %1;" : "=f"(y) : "f"(x));
    return y;
}

static __device__ __forceinline__ void cp_async16(uint32_t dst, const void* src) {
    asm volatile("cp.async.cg.shared.global [%0], [%1], 16;"
                 :: "r"(dst), "l"(src) : "memory");
}
static __device__ __forceinline__ void cp_commit() {
    asm volatile("cp.async.commit_group;" ::: "memory");
}
template <int N>
static __device__ __forceinline__ void cp_wait() {
    asm volatile("cp.async.wait_group %0;" :: "n"(N) : "memory");
}

static __device__ __forceinline__ void ldsm_x4(uint32_t* r, uint32_t addr) {
    asm volatile("ldmatrix.sync.aligned.m8n8.x4.shared.b16 {%0,%1,%2,%3}, [%4];"
                 : "=r"(r[0]), "=r"(r[1]), "=r"(r[2]), "=r"(r[3]) : "r"(addr) : "memory");
}
static __device__ __forceinline__ void ldsm_x2(uint32_t& b0, uint32_t& b1,
                                               uint32_t addr) {
    asm volatile("ldmatrix.sync.aligned.m8n8.x2.shared.b16 {%0,%1}, [%2];"
                 : "=r"(b0), "=r"(b1) : "r"(addr) : "memory");
}
static __device__ __forceinline__ void mma16816(float& c0, float& c1, float& c2,
                                                float& c3, const uint32_t* a,
                                                uint32_t b0, uint32_t b1) {
    asm volatile(
        "mma.sync.aligned.m16n8k16.row.col.f32.f16.f16.f32 "
        "{%0,%1,%2,%3}, {%4,%5,%6,%7}, {%8,%9}, {%0,%1,%2,%3};"
        : "+f"(c0), "+f"(c1), "+f"(c2), "+f"(c3)
        : "r"(a[0]), "r"(a[1]), "r"(a[2]), "r"(a[3]), "r"(b0), "r"(b1));
}

// ---------------------------------------------------------------------------
// One block = one expert; warp w owns rows [w*128, w*128+128), 8 m16 chunks.
// cp.async.cg prefetches chunk ch+1's raw floats into per-warp double-buffered
// SMEM (no registers, no L1) while chunk ch runs LDS->sigmoid->STS->ldsm->MMA.
// DRAM latency is hidden one full chunk ahead (~1700 cyc).
// ---------------------------------------------------------------------------
__global__ __launch_bounds__(THREADS, 2)
void golem_hmma_kernel(const float* __restrict__ noise,   // [E, B, H]
                       const float* __restrict__ W2,      // [E, H, H]
                       const float* __restrict__ b2,      // [E, H]
                       const float* __restrict__ W3,      // [E, H]
                       const float* __restrict__ b3,      // [E]
                       const float* __restrict__ T,       // [B]
                       const float* __restrict__ alpha,
                       const float* __restrict__ beta,
                       const float* __restrict__ bias,
                       float* __restrict__ out)           // [B,E] + [B]
{
    extern __shared__ char smem_raw_bytes[];
    Smem& s = *(Smem*)smem_raw_bytes;

    const int e   = blockIdx.x;
    const int tid = threadIdx.x;
    const int w   = tid >> 5;
    const int l   = tid & 31;

    // T_embed piggybacks on block 0
    if (e == 0) {
        float inva = __fdividef(1.0f, alpha[0]);
        float be = beta[0], bi = bias[0];
        for (int i = tid; i < NB; i += THREADS)
            out[(size_t)NB * NE + i] = inva * cosf(be * T[i] + bi);
    }

    // Stage W2[e] transposed -> Wt[o][j] fp16
    const float* W2e = W2 + (size_t)e * NH * NH;
    for (int i = tid; i < NH * NH; i += THREADS) {
        int j = i >> 6, o = i & 63;
        s.Wt[o][j] = __float2half_rn(W2e[i]);
    }
    if (tid < NH) {
        s.b2s[tid] = b2[(size_t)e * NH + tid];
        s.W3s[tid] = W3[(size_t)e * NH + tid];
    }
    __syncthreads();

    // Epilogue constants for cols o = n*8 + 2*(l&3) + {0,1}:
    //   acc = sum_o (W3[o]/2)*tanh(c_o/2) + sum_o W3[o]/2
    float   pw3h[16];
    float   w3base = 0.0f;
    __half2 pb2h[8];
    #pragma unroll
    for (int n = 0; n < 8; n++) {
        int o = n * 8 + 2 * (l & 3);
        pw3h[2 * n]     = 0.5f * s.W3s[o];
        pw3h[2 * n + 1] = 0.5f * s.W3s[o + 1];
        w3base += pw3h[2 * n] + pw3h[2 * n + 1];
        pb2h[n] = __floats2half2_rn(s.b2s[o], s.b2s[o + 1]);
    }
    const float b3e = b3[e];

    const uint32_t aBase  = smem_u32(&s.A[w][0][0]);
    const uint32_t wtBase = smem_u32(&s.Wt[0][0]);
    const uint32_t aLd = aBase + (uint32_t)(l & 15) * (LDA * 2) + (uint32_t)(l >> 4) * 16;
    const uint32_t bLd = wtBase + (uint32_t)(l & 7) * (LDA * 2) + (uint32_t)((l >> 3) & 1) * 16;

    // ---- hoist B fragments: constant per expert, loaded once ----
    uint32_t bf[8][4][2];
    #pragma unroll
    for (int n = 0; n < 8; n++)
        #pragma unroll
        for (int ks = 0; ks < 4; ks++)
            ldsm_x2(bf[n][ks][0], bf[n][ks][1],
                    bLd + (uint32_t)n * 8 * (LDA * 2) + (uint32_t)ks * 32);

    // Coalesced mapping: lane l -> sub-row (l>>4), float col (l&15)*4.
    // LDG.128 i covers rows {2i, 2i+1}: 512B contiguous per instruction.
    const float* nbase = noise + ((size_t)e * NB + (size_t)w * RPW) * NH;
    const float* gsrc  = nbase + (size_t)(l >> 4) * NH + (l & 15) * 4;
    // raw SMEM addresses for this lane (buf 0/1)
    const uint32_t rawL0 = smem_u32(&s.raw[w][0][l >> 4][(l & 15) * 4]);
    const uint32_t rawL1 = smem_u32(&s.raw[w][1][l >> 4][(l & 15) * 4]);
    // A-tile store target for this lane
    uint2* const cdst = (uint2*)((__half*)&s.A[w][0][0] + (l >> 4) * LDA + (l & 15) * 4);

    // issue cp.async for one chunk (8 x 16B per lane)
    auto prefetch = [&](int ch, uint32_t rawDst) {
        const float* g = gsrc + (size_t)ch * 16 * NH;
        #pragma unroll
        for (int i = 0; i < 8; i++)
            cp_async16(rawDst + (uint32_t)(2 * i) * (NH * 4),
                       g + (size_t)(2 * i) * NH);
        cp_commit();
    };

    // ---- pipelined main loop ----
    prefetch(0, rawL0);

    #pragma unroll 1
    for (int ch = 0; ch < CHUNKS; ch++) {
        const uint32_t rawSrc = (ch & 1) ? rawL1 : rawL0;
        if (ch + 1 < CHUNKS) {
            prefetch(ch + 1, ((ch + 1) & 1) ? rawL1 : rawL0);
            cp_wait<1>();    // chunk ch landed; ch+1 still in flight
        } else {
            cp_wait<0>();
        }
        __syncwarp();        // also orders prev ldsm reads vs our A stores

        // ---- convert 16 rows: LDS raw -> sigmoid -> fp16 A tile ----
        #pragma unroll
        for (int i = 0; i < 8; i++) {
            float4 v;
            asm volatile("ld.shared.v4.f32 {%0,%1,%2,%3}, [%4];"
                         : "=f"(v.x), "=f"(v.y), "=f"(v.z), "=f"(v.w)
                         : "r"(rawSrc + (uint32_t)(2 * i) * (NH * 4)));
            uint2 pk;
            pk.x = sig2_h(v.x, v.y);
            pk.y = sig2_h(v.z, v.w);
            cdst[(size_t)(2 * i) * (LDA / 4)] = pk;
        }
        __syncwarp();

        // ---- A fragments: 4 K-steps ----
        uint32_t a[4][4];
        #pragma unroll
        for (int ks = 0; ks < 4; ks++)
            ldsm_x4(a[ks], aLd + (uint32_t)ks * 32);

        // ---- GEMM + fused tanh epilogue per n-tile (B from registers) ----
        float acc0 = w3base, acc1 = w3base;
        #pragma unroll
        for (int n = 0; n < 8; n++) {
            float2 b2p = __half22float2(pb2h[n]);
            float c0 = b2p.x, c1 = b2p.y, c2 = b2p.x, c3 = b2p.y;
            #pragma unroll
            for (int ks = 0; ks < 4; ks++)
                mma16816(c0, c1, c2, c3, a[ks], bf[n][ks][0], bf[n][ks][1]);
            acc0 += tanhf_approx(0.5f * c0) * pw3h[2 * n];
            acc0 += tanhf_approx(0.5f * c1) * pw3h[2 * n + 1];
            acc1 += tanhf_approx(0.5f * c2) * pw3h[2 * n];
            acc1 += tanhf_approx(0.5f * c3) * pw3h[2 * n + 1];
        }

        // quad reduce over (l&3)
        acc0 += __shfl_xor_sync(0xffffffffu, acc0, 1);
        acc0 += __shfl_xor_sync(0xffffffffu, acc0, 2);
        acc1 += __shfl_xor_sync(0xffffffffu, acc1, 1);
        acc1 += __shfl_xor_sync(0xffffffffu, acc1, 2);

        if ((l & 3) == 0) {
            int r = w * RPW + ch * 16 + (l >> 2);
            out[(size_t)r * NE + e]       = acc0 + b3e;
            out[(size_t)(r + 8) * NE + e] = acc1 + b3e;
        }
    }
}

// ---------------------------------------------------------------------------
// kernel_launch — inputs: 0:T 1:noise 2:W1(dead) 3:W2 4:b2 5:W3 6:b3
//                          7:alpha 8:beta 9:bias.  Output fp32: B_mat[B,E] + T_embed[B]
// ---------------------------------------------------------------------------
extern "C" void kernel_launch(void* const* d_in, const int* in_sizes, int n_in,
                              void* d_out, int out_size)
{
    const float* T     = (const float*)d_in[0];
    const float* noise = (const float*)d_in[1];
    const float* W2    = (const float*)d_in[3];
    const float* b2    = (const float*)d_in[4];
    const float* W3    = (const float*)d_in[5];
    const float* b3    = (const float*)d_in[6];
    const float* alpha = (const float*)d_in[7];
    const float* beta  = (const float*)d_in[8];
    const float* bias  = (const float*)d_in[9];

    cudaFuncSetAttribute(golem_hmma_kernel,
                         cudaFuncAttributeMaxDynamicSharedMemorySize,
                         (int)sizeof(Smem));
    golem_hmma_kernel<<<NE, THREADS, sizeof(Smem)>>>(noise, W2, b2, W3, b3,
                                                     T, alpha, beta, bias,
                                                     (float*)d_out);
}